// round 16
// baseline (speedup 1.0000x reference)
#include <cuda_runtime.h>

#define BB 8
#define NN 2048
#define NH 8
#define MAT 16384
#define SCALE (1.0f/16384.0f)   // 1/(N*NH)
#define SA  132                 // A smem row stride (floats)
#define SBN 136                 // B smem row stride (floats)
#define NT  256                 // threads per block (8 warps)

#define SZ_G0  ((128 * SA + 128 * SBN) * 4)        // 137216 B  (k_g0 / k_out)
#define SZ_LAY ((64 * SA + 2 * 128 * SBN) * 4)     // 173056 B  (k_layer)

// ---------------- scratch (device globals) ----------------
__device__ __align__(16) float g_part[16 * BB * MAT];
__device__ __align__(16) float g_G[2][BB * MAT];
__device__ __align__(16) float g_R [BB * MAT];
__device__ __align__(16) float g_Wp[BB * NH * MAT];
__device__ __align__(16) float g_Wq[BB * MAT];
__device__ unsigned g_cntTW[4][8];   // (layer, b): TW blocks done (target 16)
__device__ unsigned g_cntW [4][8];   // (layer, b): Wsum quarters done (target 4)

// ---------------- intra-grid producer/consumer sync ----------------
__device__ __forceinline__ void arrive_cnt(unsigned* p) {
    __threadfence();
    __syncthreads();
    if (threadIdx.x == 0) atomicAdd(p, 1u);
}
__device__ __forceinline__ void wait_cnt(unsigned* p, unsigned target) {
    if (threadIdx.x == 0) {
        volatile unsigned* vp = p;
        while (*vp < target) __nanosleep(64);
    }
    __syncthreads();
    __threadfence();
}

// ---------------- tf32 helpers ----------------
__device__ __forceinline__ float tf(float x) {
    float y; asm("cvt.rna.tf32.f32 %0, %1;" : "=f"(y) : "f"(x)); return y;
}
__device__ __forceinline__ float4 tf4(float4 x) {
    x.x = tf(x.x); x.y = tf(x.y); x.z = tf(x.z); x.w = tf(x.w); return x;
}
__device__ __forceinline__ void mma8(float c[4], const float a[4], const float b[2]) {
    asm volatile(
        "mma.sync.aligned.m16n8k8.row.col.f32.tf32.tf32.f32 "
        "{%0,%1,%2,%3}, {%4,%5,%6,%7}, {%8,%9}, {%0,%1,%2,%3};"
        : "+f"(c[0]), "+f"(c[1]), "+f"(c[2]), "+f"(c[3])
        : "r"(__float_as_uint(a[0])), "r"(__float_as_uint(a[1])),
          "r"(__float_as_uint(a[2])), "r"(__float_as_uint(a[3])),
          "r"(__float_as_uint(b[0])), "r"(__float_as_uint(b[1])));
}

// ---------------- smem fills (256 threads) ----------------
__device__ __forceinline__ void fillA64(const float* __restrict__ A, int lda,
                                        float* __restrict__ As) {
#pragma unroll
    for (int i = 0; i < 8; i++) {
        int idx = threadIdx.x + NT * i;
        int m = idx >> 5, kf = (idx & 31) * 4;
        *(float4*)(As + m * SA + kf) = tf4(*(const float4*)(A + m * lda + kf));
    }
}
__device__ __forceinline__ void fillA128(const float* __restrict__ A, int lda,
                                         float* __restrict__ As) {
#pragma unroll
    for (int i = 0; i < 16; i++) {
        int idx = threadIdx.x + NT * i;
        int m = idx >> 5, kf = (idx & 31) * 4;
        *(float4*)(As + m * SA + kf) = tf4(*(const float4*)(A + m * lda + kf));
    }
}
__device__ __forceinline__ void fillAT64(const float* __restrict__ A, int lda,
                                         int moff, float* __restrict__ As) {
#pragma unroll
    for (int i = 0; i < 8; i++) {
        int idx = threadIdx.x + NT * i;
        int k = idx >> 4, mf = (idx & 15) * 4;
        float4 x = tf4(*(const float4*)(A + k * lda + moff + mf));
        As[(mf + 0) * SA + k] = x.x;
        As[(mf + 1) * SA + k] = x.y;
        As[(mf + 2) * SA + k] = x.z;
        As[(mf + 3) * SA + k] = x.w;
    }
}
__device__ __forceinline__ void fillAT128(const float* __restrict__ A, int lda,
                                          float* __restrict__ As) {
#pragma unroll
    for (int i = 0; i < 16; i++) {
        int idx = threadIdx.x + NT * i;
        int k = idx >> 5, mf = (idx & 31) * 4;
        float4 x = tf4(*(const float4*)(A + k * lda + mf));
        As[(mf + 0) * SA + k] = x.x;
        As[(mf + 1) * SA + k] = x.y;
        As[(mf + 2) * SA + k] = x.z;
        As[(mf + 3) * SA + k] = x.w;
    }
}
__device__ __forceinline__ void fillB(const float* __restrict__ B, int ldb,
                                      float* __restrict__ Bs) {
#pragma unroll
    for (int i = 0; i < 16; i++) {
        int idx = threadIdx.x + NT * i;
        int k = idx >> 5, nf = (idx & 31) * 4;
        *(float4*)(Bs + k * SBN + nf) = tf4(*(const float4*)(B + k * ldb + nf));
    }
}
// Bs[k][n] = tf(B[k*128+n] + (k==n))   -> M = I + W'
__device__ __forceinline__ void fillB_plusI(const float* __restrict__ B,
                                            float* __restrict__ Bs) {
#pragma unroll
    for (int i = 0; i < 16; i++) {
        int idx = threadIdx.x + NT * i;
        int k = idx >> 5, nf = (idx & 31) * 4;
        float4 x = *(const float4*)(B + k * 128 + nf);
        if (k == nf)     x.x += 1.0f;
        if (k == nf + 1) x.y += 1.0f;
        if (k == nf + 2) x.z += 1.0f;
        if (k == nf + 3) x.w += 1.0f;
        *(float4*)(Bs + k * SBN + nf) = tf4(x);
    }
}
// transposed B: Bs[k][n] = B[n*ldb + k]   (V^T)
__device__ __forceinline__ void fillBT(const float* __restrict__ B, int ldb,
                                       float* __restrict__ Bs) {
#pragma unroll
    for (int i = 0; i < 16; i++) {
        int idx = threadIdx.x + NT * i;
        int n = idx >> 5, kf = (idx & 31) * 4;
        float4 x = tf4(*(const float4*)(B + n * ldb + kf));
        Bs[(kf + 0) * SBN + n] = x.x;
        Bs[(kf + 1) * SBN + n] = x.y;
        Bs[(kf + 2) * SBN + n] = x.z;
        Bs[(kf + 3) * SBN + n] = x.w;
    }
}

// ---------------- compute cores ----------------
__device__ __forceinline__ void compute64(const float* __restrict__ As,
                                          const float* __restrict__ Bs,
                                          float acc[2][4][4]) {
    const int lane = threadIdx.x & 31, warp = threadIdx.x >> 5;
    const int mr = (warp & 1) * 32, nc = (warp >> 1) * 32;
    const int ar = lane >> 2, ac = lane & 3;
    const int bk = lane & 3,  bn = lane >> 2;
#pragma unroll
    for (int kk = 0; kk < 128; kk += 8) {
        float a[2][4];
#pragma unroll
        for (int i = 0; i < 2; i++) {
            const float* p = As + (mr + 16 * i + ar) * SA + kk + ac;
            a[i][0] = p[0]; a[i][1] = p[8 * SA]; a[i][2] = p[4]; a[i][3] = p[8 * SA + 4];
        }
#pragma unroll
        for (int j = 0; j < 4; j++) {
            const float* qp = Bs + (kk + bk) * SBN + nc + 8 * j + bn;
            float b[2] = { qp[0], qp[4 * SBN] };
            mma8(acc[0][j], a[0], b);
            mma8(acc[1][j], a[1], b);
        }
    }
}
__device__ __forceinline__ void compute128(const float* __restrict__ As,
                                           const float* __restrict__ Bs,
                                           float acc[2][8][4]) {
    const int lane = threadIdx.x & 31, warp = threadIdx.x >> 5;
    const int mr = (warp & 3) * 32, nc = (warp >> 2) * 64;
    const int ar = lane >> 2, ac = lane & 3;
    const int bk = lane & 3,  bn = lane >> 2;
#pragma unroll
    for (int kk = 0; kk < 128; kk += 8) {
        float a[2][4];
#pragma unroll
        for (int i = 0; i < 2; i++) {
            const float* p = As + (mr + 16 * i + ar) * SA + kk + ac;
            a[i][0] = p[0]; a[i][1] = p[8 * SA]; a[i][2] = p[4]; a[i][3] = p[8 * SA + 4];
        }
#pragma unroll
        for (int j = 0; j < 8; j++) {
            const float* qp = Bs + (kk + bk) * SBN + nc + 8 * j + bn;
            float b[2] = { qp[0], qp[4 * SBN] };
            mma8(acc[0][j], a[0], b);
            mma8(acc[1][j], a[1], b);
        }
    }
}
__device__ __forceinline__ void zacc64(float a[2][4][4]) {
#pragma unroll
    for (int i = 0; i < 2; i++)
#pragma unroll
        for (int j = 0; j < 4; j++)
#pragma unroll
            for (int r = 0; r < 4; r++) a[i][j][r] = 0.0f;
}
__device__ __forceinline__ void zacc128(float a[2][8][4]) {
#pragma unroll
    for (int i = 0; i < 2; i++)
#pragma unroll
        for (int j = 0; j < 8; j++)
#pragma unroll
            for (int r = 0; r < 4; r++) a[i][j][r] = 0.0f;
}

// ---------------- epilogues ----------------
__device__ __forceinline__ void epi64(float* __restrict__ C,
                                      const float* __restrict__ a1,
                                      const float* __restrict__ a2,
                                      float acc[2][4][4]) {
    const int lane = threadIdx.x & 31, warp = threadIdx.x >> 5;
    const int r0 = (warp & 1) * 32 + (lane >> 2);
    const int c0 = (warp >> 1) * 32 + 2 * (lane & 3);
#pragma unroll
    for (int i = 0; i < 2; i++)
#pragma unroll
        for (int j = 0; j < 4; j++) {
            int r = r0 + 16 * i, c = c0 + 8 * j;
            float2 lo = make_float2(acc[i][j][0], acc[i][j][1]);
            float2 hi = make_float2(acc[i][j][2], acc[i][j][3]);
            if (a1) {
                float2 x = *(const float2*)(a1 + r * 128 + c);
                float2 y = *(const float2*)(a1 + (r + 8) * 128 + c);
                lo.x += x.x; lo.y += x.y; hi.x += y.x; hi.y += y.y;
            }
            if (a2) {
                float2 x = *(const float2*)(a2 + r * 128 + c);
                float2 y = *(const float2*)(a2 + (r + 8) * 128 + c);
                lo.x += x.x; lo.y += x.y; hi.x += y.x; hi.y += y.y;
            }
            *(float2*)(C + r * 128 + c)       = lo;
            *(float2*)(C + (r + 8) * 128 + c) = hi;
        }
}
__device__ __forceinline__ void epi128(float* __restrict__ C,
                                       float acc[2][8][4]) {
    const int lane = threadIdx.x & 31, warp = threadIdx.x >> 5;
    const int r0 = (warp & 3) * 32 + (lane >> 2);
    const int c0 = (warp >> 2) * 64 + 2 * (lane & 3);
#pragma unroll
    for (int i = 0; i < 2; i++)
#pragma unroll
        for (int j = 0; j < 8; j++) {
            int r = r0 + 16 * i, c = c0 + 8 * j;
            *(float2*)(C + r * 128 + c)       = make_float2(acc[i][j][0], acc[i][j][1]);
            *(float2*)(C + (r + 8) * 128 + c) = make_float2(acc[i][j][2], acc[i][j][3]);
        }
}
__device__ __forceinline__ void storeT64(float* __restrict__ As,
                                         float acc[2][4][4]) {
    const int lane = threadIdx.x & 31, warp = threadIdx.x >> 5;
    const int r0 = (warp & 1) * 32 + (lane >> 2);
    const int c0 = (warp >> 1) * 32 + 2 * (lane & 3);
#pragma unroll
    for (int i = 0; i < 2; i++)
#pragma unroll
        for (int j = 0; j < 4; j++) {
            int r = r0 + 16 * i, c = c0 + 8 * j;
            As[r * SA + c]           = tf(acc[i][j][0]);
            As[r * SA + c + 1]       = tf(acc[i][j][1]);
            As[(r + 8) * SA + c]     = tf(acc[i][j][2]);
            As[(r + 8) * SA + c + 1] = tf(acc[i][j][3]);
        }
}
__device__ __forceinline__ void storeT64_add(float* __restrict__ As,
                                             float acc[2][4][4],
                                             const float* __restrict__ add) {
    const int lane = threadIdx.x & 31, warp = threadIdx.x >> 5;
    const int r0 = (warp & 1) * 32 + (lane >> 2);
    const int c0 = (warp >> 1) * 32 + 2 * (lane & 3);
#pragma unroll
    for (int i = 0; i < 2; i++)
#pragma unroll
        for (int j = 0; j < 4; j++) {
            int r = r0 + 16 * i, c = c0 + 8 * j;
            float2 x = *(const float2*)(add + r * 128 + c);
            float2 y = *(const float2*)(add + (r + 8) * 128 + c);
            As[r * SA + c]           = tf(acc[i][j][0] + x.x);
            As[r * SA + c + 1]       = tf(acc[i][j][1] + x.y);
            As[(r + 8) * SA + c]     = tf(acc[i][j][2] + y.x);
            As[(r + 8) * SA + c + 1] = tf(acc[i][j][3] + y.y);
        }
}
__device__ __forceinline__ void storeT128(float* __restrict__ As,
                                          float acc[2][8][4]) {
    const int lane = threadIdx.x & 31, warp = threadIdx.x >> 5;
    const int r0 = (warp & 3) * 32 + (lane >> 2);
    const int c0 = (warp >> 2) * 64 + 2 * (lane & 3);
#pragma unroll
    for (int i = 0; i < 2; i++)
#pragma unroll
        for (int j = 0; j < 8; j++) {
            int r = r0 + 16 * i, c = c0 + 8 * j;
            As[r * SA + c]           = tf(acc[i][j][0]);
            As[r * SA + c + 1]       = tf(acc[i][j][1]);
            As[(r + 8) * SA + c]     = tf(acc[i][j][2]);
            As[(r + 8) * SA + c + 1] = tf(acc[i][j][3]);
        }
}

// ---------------- kernels ----------------

// part[chunk,b] = Zc^T @ Zc  (full 128-row tile)   grid (16, 8)
__global__ __launch_bounds__(NT) void k_g0(const float* __restrict__ Z,
                                           float* __restrict__ part) {
    extern __shared__ float sm[];
    float* As = sm; float* Bs = sm + 128 * SA;
    int chunk = blockIdx.x, b = blockIdx.y;
    const float* Zc = Z + (b * NN + chunk * 128) * 128;
    fillAT128(Zc, 128, As);
    fillB(Zc, 128, Bs);
    __syncthreads();
    float acc[2][8][4]; zacc128(acc);
    compute128(As, Bs, acc);
    epi128(part + (chunk * BB + b) * MAT, acc);
}

// G[0] = sum over 16 chunks (float4)          grid (256) x 128 thr
__global__ __launch_bounds__(128) void k_reduce(const float* __restrict__ part,
                                                float* __restrict__ G) {
    int e = (blockIdx.x * 128 + threadIdx.x) * 4;
    int b = e >> 14, i = e & 16383;
    float4 s = make_float4(0.f, 0.f, 0.f, 0.f);
#pragma unroll
    for (int c = 0; c < 16; c++) {
        float4 x = *(const float4*)(part + (c * BB + b) * MAT + i);
        s.x += x.x; s.y += x.y; s.z += x.z; s.w += x.w;
    }
    *(float4*)(G + e) = s;
}

// one kernel = whole layer: TW (bids 0..127) + Wsum (128..159) + C (160..191)
// l==3 launched with 160 blocks (no C).
__global__ __launch_bounds__(NT) void k_layer(const float* __restrict__ q,
                                              const float* __restrict__ v,
                                              const float* __restrict__ G,
                                              float* __restrict__ Gn,
                                              float* __restrict__ R,
                                              float* __restrict__ Wp,
                                              float* __restrict__ Wq, int l) {
    extern __shared__ float sm[];
    const int bid = blockIdx.x;

    if (bid < 128) {
        // ---- TW: T = Q@G, W_j = T@V^T ----
        float* As  = sm;
        float* BsG = sm + 64 * SA;
        float* BsV = BsG + 128 * SBN;
        int j = bid & 7, b = (bid >> 3) & 7, mh = bid >> 6;
        fillA64(q + (l * NH + j) * MAT + mh * 64 * 128, 128, As);
        fillB(G + b * MAT, 128, BsG);
        fillBT(v + (l * NH + j) * MAT, 128, BsV);
        __syncthreads();
        float acc[2][4][4]; zacc64(acc);
        compute64(As, BsG, acc);
        __syncthreads();
        storeT64(As, acc);
        __syncthreads();
        zacc64(acc);
        compute64(As, BsV, acc);
        epi64(Wp + (b * NH + j) * MAT + mh * 64 * 128, 0, 0, acc);
        arrive_cnt(&g_cntTW[l][b]);
    } else if (bid < 160) {
        // ---- Wsum quarter: W'[b] = SCALE * sum_j Wp[b,j] ----
        int idx = bid - 128, b = idx >> 2, qt = idx & 3;
        wait_cnt(&g_cntTW[l][b], 16);
#pragma unroll
        for (int i = 0; i < 4; i++) {
            int ii = qt * 4096 + (i * NT + threadIdx.x) * 4;   // same order as old k_Wsum
            float4 s = make_float4(0.f, 0.f, 0.f, 0.f);
#pragma unroll
            for (int j = 0; j < NH; j++) {
                float4 x = *(const float4*)(Wp + (b * NH + j) * MAT + ii);
                s.x += x.x; s.y += x.y; s.z += x.z; s.w += x.w;
            }
            s.x *= SCALE; s.y *= SCALE; s.z *= SCALE; s.w *= SCALE;
            *(float4*)(Wq + b * MAT + ii) = s;
            if (l == 0) *(float4*)(R + b * MAT + ii) = s;
        }
        arrive_cnt(&g_cntW[l][b]);
    } else {
        // ---- C: which 0: Gnext slab = (M^T)_slab G M ; which 1: R update ----
        int idx = bid - 160, which = idx >> 4, r2 = idx & 15;
        int mh = r2 & 1, b = r2 >> 1;
        float* As = sm; float* Bs = sm + 64 * SA;
        if (which == 0) {
            fillB(G + b * MAT, 128, Bs);             // old G: pre-spin OK
            wait_cnt(&g_cntW[l][b], 4);
            fillAT64(Wq + b * MAT, 128, mh * 64, As);
            __syncthreads();
            float acc[2][4][4]; zacc64(acc);
            compute64(As, Bs, acc);
            __syncthreads();
            storeT64_add(As, acc, G + b * MAT + mh * 64 * 128);
            fillB_plusI(Wq + b * MAT, Bs);
            __syncthreads();
            float acc2[2][4][4]; zacc64(acc2);
            compute64(As, Bs, acc2);
            epi64(Gn + b * MAT + mh * 64 * 128, 0, 0, acc2);
        } else {
            if (l == 0) return;                      // R = W' already written by Wsum
            float* Rp = R + b * MAT + mh * 64 * 128;
            fillA64(Rp, 128, As);                    // old R: pre-spin OK
            wait_cnt(&g_cntW[l][b], 4);
            fillB(Wq + b * MAT, 128, Bs);
            __syncthreads();
            float acc[2][4][4]; zacc64(acc);
            compute64(As, Bs, acc);
            epi64(Rp, Rp, Wq + b * MAT + mh * 64 * 128, acc);
        }
    }
}

// out tile (128 rows): Y = Zt + Zt@R2 (exact in regs), out = Y + Y@W'3
// grid (16, 8); also resets the flag counters for the next graph replay.
__global__ __launch_bounds__(NT) void k_out(const float* __restrict__ Z,
                                            const float* __restrict__ R,
                                            const float* __restrict__ Wq,
                                            float* __restrict__ out) {
    extern __shared__ float sm[];
    if (blockIdx.x == 0 && blockIdx.y == 0) {
        if (threadIdx.x < 32)      ((unsigned*)g_cntTW)[threadIdx.x] = 0;
        else if (threadIdx.x < 64) ((unsigned*)g_cntW)[threadIdx.x - 32] = 0;
    }
    float* As = sm; float* Bs = sm + 128 * SA;
    int tile = blockIdx.x, b = blockIdx.y;
    const float* Zt = Z + (b * NN + tile * 128) * 128;
    fillA128(Zt, 128, As);
    fillB(R + b * MAT, 128, Bs);
    __syncthreads();
    float acc[2][8][4]; zacc128(acc);
    compute128(As, Bs, acc);

    const int lane = threadIdx.x & 31, warp = threadIdx.x >> 5;
    const int r0 = (warp & 3) * 32 + (lane >> 2);
    const int c0 = (warp >> 2) * 64 + 2 * (lane & 3);
#pragma unroll
    for (int i = 0; i < 2; i++)
#pragma unroll
        for (int j = 0; j < 8; j++) {
            int r = r0 + 16 * i, c = c0 + 8 * j;
            acc[i][j][0] += Zt[r * 128 + c];
            acc[i][j][1] += Zt[r * 128 + c + 1];
            acc[i][j][2] += Zt[(r + 8) * 128 + c];
            acc[i][j][3] += Zt[(r + 8) * 128 + c + 1];
        }
    __syncthreads();
    storeT128(As, acc);              // As <- tf(Y)
    fillB(Wq + b * MAT, 128, Bs);    // Bs <- W'_3
    __syncthreads();
    float acc2[2][8][4]; zacc128(acc2);
    compute128(As, Bs, acc2);

    float* Ct = out + (b * NN + tile * 128) * 128;
#pragma unroll
    for (int i = 0; i < 2; i++)
#pragma unroll
        for (int j = 0; j < 8; j++) {
            int r = r0 + 16 * i, c = c0 + 8 * j;
            *(float2*)(Ct + r * 128 + c) =
                make_float2(acc[i][j][0] + acc2[i][j][0], acc[i][j][1] + acc2[i][j][1]);
            *(float2*)(Ct + (r + 8) * 128 + c) =
                make_float2(acc[i][j][2] + acc2[i][j][2], acc[i][j][3] + acc2[i][j][3]);
        }
}

// ---------------- host ----------------
extern "C" void kernel_launch(void* const* d_in, const int* in_sizes, int n_in,
                              void* d_out, int out_size) {
    const float* Z = (const float*)d_in[0];
    const float* v = (const float*)d_in[1];
    const float* q = (const float*)d_in[2];
    float* out = (float*)d_out;

    cudaFuncSetAttribute(k_g0,    cudaFuncAttributeMaxDynamicSharedMemorySize, SZ_G0);
    cudaFuncSetAttribute(k_out,   cudaFuncAttributeMaxDynamicSharedMemorySize, SZ_G0);
    cudaFuncSetAttribute(k_layer, cudaFuncAttributeMaxDynamicSharedMemorySize, SZ_LAY);

    float *pPart, *pG, *pR, *pWp, *pWq;
    cudaGetSymbolAddress((void**)&pPart, g_part);
    cudaGetSymbolAddress((void**)&pG,  g_G);
    cudaGetSymbolAddress((void**)&pR,  g_R);
    cudaGetSymbolAddress((void**)&pWp, g_Wp);
    cudaGetSymbolAddress((void**)&pWq, g_Wq);

    float* Gbuf[2] = { pG, pG + BB * MAT };

    k_g0    <<<dim3(16, BB), NT, SZ_G0>>>(Z, pPart);
    k_reduce<<<256, 128>>>(pPart, Gbuf[0]);

    int cur = 0;
    for (int l = 0; l < 3; l++) {
        k_layer<<<192, NT, SZ_LAY>>>(q, v, Gbuf[cur], Gbuf[cur ^ 1],
                                     pR, pWp, pWq, l);
        cur ^= 1;
    }
    // layer 3: TW + Wsum only (no C blocks)
    k_layer<<<160, NT, SZ_LAY>>>(q, v, Gbuf[cur], Gbuf[cur ^ 1],
                                 pR, pWp, pWq, 3);

    k_out<<<dim3(16, BB), NT, SZ_G0>>>(Z, pR, pWq, out);
}

// round 17
// speedup vs baseline: 1.0401x; 1.0401x over previous
#include <cuda_runtime.h>

#define BB 8
#define NN 2048
#define NH 8
#define MAT 16384
#define SCALE (1.0f/16384.0f)   // 1/(N*NH)
#define SA  132                 // A smem row stride (floats)
#define SBN 136                 // B smem row stride (floats)
#define NT  256                 // threads per block (8 warps)

#define SZ_C   ((64 * SA + 128 * SBN) * 4)         // 103424 B  (k_C)
#define SZ_BIG ((128 * SA + 128 * SBN) * 4)        // 137216 B  (k_g0 / k_out)
#define SZ_TW  ((64 * SA + 2 * 128 * SBN) * 4)     // 173056 B  (k_TW)

// ---------------- scratch (device globals) ----------------
__device__ __align__(16) float g_part[16 * BB * MAT];
__device__ __align__(16) float g_G[2][BB * MAT];
__device__ __align__(16) float g_R [BB * MAT];
__device__ __align__(16) float g_Wp[BB * NH * MAT];
__device__ __align__(16) float g_Wq[BB * MAT];

// ---------------- tf32 helpers ----------------
__device__ __forceinline__ float tf(float x) {
    float y; asm("cvt.rna.tf32.f32 %0, %1;" : "=f"(y) : "f"(x)); return y;
}
__device__ __forceinline__ float4 tf4(float4 x) {
    x.x = tf(x.x); x.y = tf(x.y); x.z = tf(x.z); x.w = tf(x.w); return x;
}
// NOT volatile: pure register computation; lets ptxas pipeline LDS across MMAs.
// Per-accumulator MMA order is fixed by the data dependence on c[], so the
// numerical result is bit-identical to the volatile version.
__device__ __forceinline__ void mma8(float c[4], const float a[4], const float b[2]) {
    asm("mma.sync.aligned.m16n8k8.row.col.f32.tf32.tf32.f32 "
        "{%0,%1,%2,%3}, {%4,%5,%6,%7}, {%8,%9}, {%0,%1,%2,%3};"
        : "+f"(c[0]), "+f"(c[1]), "+f"(c[2]), "+f"(c[3])
        : "r"(__float_as_uint(a[0])), "r"(__float_as_uint(a[1])),
          "r"(__float_as_uint(a[2])), "r"(__float_as_uint(a[3])),
          "r"(__float_as_uint(b[0])), "r"(__float_as_uint(b[1])));
}

// ---------------- smem fills (256 threads) ----------------
__device__ __forceinline__ void fillA64(const float* __restrict__ A, int lda,
                                        float* __restrict__ As) {
#pragma unroll
    for (int i = 0; i < 8; i++) {
        int idx = threadIdx.x + NT * i;
        int m = idx >> 5, kf = (idx & 31) * 4;
        *(float4*)(As + m * SA + kf) = tf4(*(const float4*)(A + m * lda + kf));
    }
}
__device__ __forceinline__ void fillA128(const float* __restrict__ A, int lda,
                                         float* __restrict__ As) {
#pragma unroll
    for (int i = 0; i < 16; i++) {
        int idx = threadIdx.x + NT * i;
        int m = idx >> 5, kf = (idx & 31) * 4;
        *(float4*)(As + m * SA + kf) = tf4(*(const float4*)(A + m * lda + kf));
    }
}
__device__ __forceinline__ void fillAT64(const float* __restrict__ A, int lda,
                                         int moff, float* __restrict__ As) {
#pragma unroll
    for (int i = 0; i < 8; i++) {
        int idx = threadIdx.x + NT * i;
        int k = idx >> 4, mf = (idx & 15) * 4;
        float4 x = tf4(*(const float4*)(A + k * lda + moff + mf));
        As[(mf + 0) * SA + k] = x.x;
        As[(mf + 1) * SA + k] = x.y;
        As[(mf + 2) * SA + k] = x.z;
        As[(mf + 3) * SA + k] = x.w;
    }
}
__device__ __forceinline__ void fillAT128(const float* __restrict__ A, int lda,
                                          float* __restrict__ As) {
#pragma unroll
    for (int i = 0; i < 16; i++) {
        int idx = threadIdx.x + NT * i;
        int k = idx >> 5, mf = (idx & 31) * 4;
        float4 x = tf4(*(const float4*)(A + k * lda + mf));
        As[(mf + 0) * SA + k] = x.x;
        As[(mf + 1) * SA + k] = x.y;
        As[(mf + 2) * SA + k] = x.z;
        As[(mf + 3) * SA + k] = x.w;
    }
}
__device__ __forceinline__ void fillB(const float* __restrict__ B, int ldb,
                                      float* __restrict__ Bs) {
#pragma unroll
    for (int i = 0; i < 16; i++) {
        int idx = threadIdx.x + NT * i;
        int k = idx >> 5, nf = (idx & 31) * 4;
        *(float4*)(Bs + k * SBN + nf) = tf4(*(const float4*)(B + k * ldb + nf));
    }
}
// Bs[k][n] = tf(B[k*128+n] + (k==n))   -> M = I + W'
__device__ __forceinline__ void fillB_plusI(const float* __restrict__ B,
                                            float* __restrict__ Bs) {
#pragma unroll
    for (int i = 0; i < 16; i++) {
        int idx = threadIdx.x + NT * i;
        int k = idx >> 5, nf = (idx & 31) * 4;
        float4 x = *(const float4*)(B + k * 128 + nf);
        if (k == nf)     x.x += 1.0f;
        if (k == nf + 1) x.y += 1.0f;
        if (k == nf + 2) x.z += 1.0f;
        if (k == nf + 3) x.w += 1.0f;
        *(float4*)(Bs + k * SBN + nf) = tf4(x);
    }
}
// transposed B: Bs[k][n] = B[n*ldb + k]   (V^T)
__device__ __forceinline__ void fillBT(const float* __restrict__ B, int ldb,
                                       float* __restrict__ Bs) {
#pragma unroll
    for (int i = 0; i < 16; i++) {
        int idx = threadIdx.x + NT * i;
        int n = idx >> 5, kf = (idx & 31) * 4;
        float4 x = tf4(*(const float4*)(B + n * ldb + kf));
        Bs[(kf + 0) * SBN + n] = x.x;
        Bs[(kf + 1) * SBN + n] = x.y;
        Bs[(kf + 2) * SBN + n] = x.z;
        Bs[(kf + 3) * SBN + n] = x.w;
    }
}

// ---------------- compute cores ----------------
__device__ __forceinline__ void compute64(const float* __restrict__ As,
                                          const float* __restrict__ Bs,
                                          float acc[2][4][4]) {
    const int lane = threadIdx.x & 31, warp = threadIdx.x >> 5;
    const int mr = (warp & 1) * 32, nc = (warp >> 1) * 32;
    const int ar = lane >> 2, ac = lane & 3;
    const int bk = lane & 3,  bn = lane >> 2;
#pragma unroll
    for (int kk = 0; kk < 128; kk += 8) {
        float a[2][4];
#pragma unroll
        for (int i = 0; i < 2; i++) {
            const float* p = As + (mr + 16 * i + ar) * SA + kk + ac;
            a[i][0] = p[0]; a[i][1] = p[8 * SA]; a[i][2] = p[4]; a[i][3] = p[8 * SA + 4];
        }
#pragma unroll
        for (int j = 0; j < 4; j++) {
            const float* qp = Bs + (kk + bk) * SBN + nc + 8 * j + bn;
            float b[2] = { qp[0], qp[4 * SBN] };
            mma8(acc[0][j], a[0], b);
            mma8(acc[1][j], a[1], b);
        }
    }
}
__device__ __forceinline__ void compute128(const float* __restrict__ As,
                                           const float* __restrict__ Bs,
                                           float acc[2][8][4]) {
    const int lane = threadIdx.x & 31, warp = threadIdx.x >> 5;
    const int mr = (warp & 3) * 32, nc = (warp >> 2) * 64;
    const int ar = lane >> 2, ac = lane & 3;
    const int bk = lane & 3,  bn = lane >> 2;
#pragma unroll
    for (int kk = 0; kk < 128; kk += 8) {
        float a[2][4];
#pragma unroll
        for (int i = 0; i < 2; i++) {
            const float* p = As + (mr + 16 * i + ar) * SA + kk + ac;
            a[i][0] = p[0]; a[i][1] = p[8 * SA]; a[i][2] = p[4]; a[i][3] = p[8 * SA + 4];
        }
#pragma unroll
        for (int j = 0; j < 8; j++) {
            const float* qp = Bs + (kk + bk) * SBN + nc + 8 * j + bn;
            float b[2] = { qp[0], qp[4 * SBN] };
            mma8(acc[0][j], a[0], b);
            mma8(acc[1][j], a[1], b);
        }
    }
}
__device__ __forceinline__ void zacc64(float a[2][4][4]) {
#pragma unroll
    for (int i = 0; i < 2; i++)
#pragma unroll
        for (int j = 0; j < 4; j++)
#pragma unroll
            for (int r = 0; r < 4; r++) a[i][j][r] = 0.0f;
}
__device__ __forceinline__ void zacc128(float a[2][8][4]) {
#pragma unroll
    for (int i = 0; i < 2; i++)
#pragma unroll
        for (int j = 0; j < 8; j++)
#pragma unroll
            for (int r = 0; r < 4; r++) a[i][j][r] = 0.0f;
}

// ---------------- epilogues ----------------
__device__ __forceinline__ void epi64(float* __restrict__ C,
                                      const float* __restrict__ a1,
                                      const float* __restrict__ a2,
                                      float acc[2][4][4]) {
    const int lane = threadIdx.x & 31, warp = threadIdx.x >> 5;
    const int r0 = (warp & 1) * 32 + (lane >> 2);
    const int c0 = (warp >> 1) * 32 + 2 * (lane & 3);
#pragma unroll
    for (int i = 0; i < 2; i++)
#pragma unroll
        for (int j = 0; j < 4; j++) {
            int r = r0 + 16 * i, c = c0 + 8 * j;
            float2 lo = make_float2(acc[i][j][0], acc[i][j][1]);
            float2 hi = make_float2(acc[i][j][2], acc[i][j][3]);
            if (a1) {
                float2 x = *(const float2*)(a1 + r * 128 + c);
                float2 y = *(const float2*)(a1 + (r + 8) * 128 + c);
                lo.x += x.x; lo.y += x.y; hi.x += y.x; hi.y += y.y;
            }
            if (a2) {
                float2 x = *(const float2*)(a2 + r * 128 + c);
                float2 y = *(const float2*)(a2 + (r + 8) * 128 + c);
                lo.x += x.x; lo.y += x.y; hi.x += y.x; hi.y += y.y;
            }
            *(float2*)(C + r * 128 + c)       = lo;
            *(float2*)(C + (r + 8) * 128 + c) = hi;
        }
}
__device__ __forceinline__ void epi128(float* __restrict__ C,
                                       float acc[2][8][4]) {
    const int lane = threadIdx.x & 31, warp = threadIdx.x >> 5;
    const int r0 = (warp & 3) * 32 + (lane >> 2);
    const int c0 = (warp >> 2) * 64 + 2 * (lane & 3);
#pragma unroll
    for (int i = 0; i < 2; i++)
#pragma unroll
        for (int j = 0; j < 8; j++) {
            int r = r0 + 16 * i, c = c0 + 8 * j;
            *(float2*)(C + r * 128 + c)       = make_float2(acc[i][j][0], acc[i][j][1]);
            *(float2*)(C + (r + 8) * 128 + c) = make_float2(acc[i][j][2], acc[i][j][3]);
        }
}
__device__ __forceinline__ void storeT64(float* __restrict__ As,
                                         float acc[2][4][4]) {
    const int lane = threadIdx.x & 31, warp = threadIdx.x >> 5;
    const int r0 = (warp & 1) * 32 + (lane >> 2);
    const int c0 = (warp >> 1) * 32 + 2 * (lane & 3);
#pragma unroll
    for (int i = 0; i < 2; i++)
#pragma unroll
        for (int j = 0; j < 4; j++) {
            int r = r0 + 16 * i, c = c0 + 8 * j;
            As[r * SA + c]           = tf(acc[i][j][0]);
            As[r * SA + c + 1]       = tf(acc[i][j][1]);
            As[(r + 8) * SA + c]     = tf(acc[i][j][2]);
            As[(r + 8) * SA + c + 1] = tf(acc[i][j][3]);
        }
}
__device__ __forceinline__ void storeT64_add(float* __restrict__ As,
                                             float acc[2][4][4],
                                             const float* __restrict__ add) {
    const int lane = threadIdx.x & 31, warp = threadIdx.x >> 5;
    const int r0 = (warp & 1) * 32 + (lane >> 2);
    const int c0 = (warp >> 1) * 32 + 2 * (lane & 3);
#pragma unroll
    for (int i = 0; i < 2; i++)
#pragma unroll
        for (int j = 0; j < 4; j++) {
            int r = r0 + 16 * i, c = c0 + 8 * j;
            float2 x = *(const float2*)(add + r * 128 + c);
            float2 y = *(const float2*)(add + (r + 8) * 128 + c);
            As[r * SA + c]           = tf(acc[i][j][0] + x.x);
            As[r * SA + c + 1]       = tf(acc[i][j][1] + x.y);
            As[(r + 8) * SA + c]     = tf(acc[i][j][2] + y.x);
            As[(r + 8) * SA + c + 1] = tf(acc[i][j][3] + y.y);
        }
}
__device__ __forceinline__ void storeT128(float* __restrict__ As,
                                          float acc[2][8][4]) {
    const int lane = threadIdx.x & 31, warp = threadIdx.x >> 5;
    const int r0 = (warp & 3) * 32 + (lane >> 2);
    const int c0 = (warp >> 2) * 64 + 2 * (lane & 3);
#pragma unroll
    for (int i = 0; i < 2; i++)
#pragma unroll
        for (int j = 0; j < 8; j++) {
            int r = r0 + 16 * i, c = c0 + 8 * j;
            As[r * SA + c]           = tf(acc[i][j][0]);
            As[r * SA + c + 1]       = tf(acc[i][j][1]);
            As[(r + 8) * SA + c]     = tf(acc[i][j][2]);
            As[(r + 8) * SA + c + 1] = tf(acc[i][j][3]);
        }
}

// ---------------- kernels ----------------

// part[chunk,b] = Zc^T @ Zc  (full 128-row tile)   grid (16, 8)
__global__ __launch_bounds__(NT) void k_g0(const float* __restrict__ Z,
                                           float* __restrict__ part) {
    extern __shared__ float sm[];
    float* As = sm; float* Bs = sm + 128 * SA;
    int chunk = blockIdx.x, b = blockIdx.y;
    const float* Zc = Z + (b * NN + chunk * 128) * 128;
    fillAT128(Zc, 128, As);
    fillB(Zc, 128, Bs);
    __syncthreads();
    float acc[2][8][4]; zacc128(acc);
    compute128(As, Bs, acc);
    epi128(part + (chunk * BB + b) * MAT, acc);
}

// G[0] = sum over 16 chunks (float4)          grid (256) x 128 thr
__global__ __launch_bounds__(128) void k_reduce(const float* __restrict__ part,
                                                float* __restrict__ G) {
    int e = (blockIdx.x * 128 + threadIdx.x) * 4;
    int b = e >> 14, i = e & 16383;
    float4 s = make_float4(0.f, 0.f, 0.f, 0.f);
#pragma unroll
    for (int c = 0; c < 16; c++) {
        float4 x = *(const float4*)(part + (c * BB + b) * MAT + i);
        s.x += x.x; s.y += x.y; s.z += x.z; s.w += x.w;
    }
    *(float4*)(G + e) = s;
}

// fused T = Q@G, W = T@V^T  (dedicated V buffer)   grid (8, 8, 2)
__global__ __launch_bounds__(NT) void k_TW(const float* __restrict__ q,
                                           const float* __restrict__ v,
                                           const float* __restrict__ G,
                                           float* __restrict__ Wp, int l) {
    extern __shared__ float sm[];
    float* As  = sm;
    float* BsG = sm + 64 * SA;
    float* BsV = BsG + 128 * SBN;
    int j = blockIdx.x, b = blockIdx.y, mh = blockIdx.z;
    fillA64(q + (l * NH + j) * MAT + mh * 64 * 128, 128, As);
    fillB(G + b * MAT, 128, BsG);
    fillBT(v + (l * NH + j) * MAT, 128, BsV);
    __syncthreads();
    float acc[2][4][4]; zacc64(acc);
    compute64(As, BsG, acc);
    __syncthreads();                 // GEMM1 reads of As complete
    storeT64(As, acc);
    __syncthreads();
    zacc64(acc);
    compute64(As, BsV, acc);
    epi64(Wp + (b * NH + j) * MAT + mh * 64 * 128, 0, 0, acc);
}

// W'[b] = SCALE * sum_j Wp[b,j]; layer 0 also R = W'   grid (256) x 128 thr
__global__ __launch_bounds__(128) void k_Wsum(const float* __restrict__ Wp,
                                              float* __restrict__ Wq,
                                              float* __restrict__ R, int copyR) {
    int e = (blockIdx.x * 128 + threadIdx.x) * 4;
    int b = e >> 14, i = e & 16383;
    float4 s = make_float4(0.f, 0.f, 0.f, 0.f);
#pragma unroll
    for (int j = 0; j < NH; j++) {
        float4 x = *(const float4*)(Wp + (b * NH + j) * MAT + i);
        s.x += x.x; s.y += x.y; s.z += x.z; s.w += x.w;
    }
    s.x *= SCALE; s.y *= SCALE; s.z *= SCALE; s.w *= SCALE;
    *(float4*)(Wq + e) = s;
    if (copyR) *(float4*)(R + e) = s;
}

// C: z=0: Gnext slab = (M^T)_slab G M  (chained GEMMs, M = I + W')
//    z=1: R slab = R + W' + R@W'
// grid (2, 8, zz)
__global__ __launch_bounds__(NT) void k_C(const float* __restrict__ Wq,
                                          const float* __restrict__ G,
                                          float* __restrict__ R,
                                          float* __restrict__ Gn) {
    extern __shared__ float sm[];
    float* As = sm; float* Bs = sm + 64 * SA;
    int mh = blockIdx.x, b = blockIdx.y, which = blockIdx.z;
    if (which == 0) {
        fillAT64(Wq + b * MAT, 128, mh * 64, As);
        fillB(G + b * MAT, 128, Bs);
        __syncthreads();
        float acc[2][4][4]; zacc64(acc);
        compute64(As, Bs, acc);
        __syncthreads();
        storeT64_add(As, acc, G + b * MAT + mh * 64 * 128);
        fillB_plusI(Wq + b * MAT, Bs);
        __syncthreads();
        float acc2[2][4][4]; zacc64(acc2);
        compute64(As, Bs, acc2);
        epi64(Gn + b * MAT + mh * 64 * 128, 0, 0, acc2);
    } else {
        float* Rp = R + b * MAT + mh * 64 * 128;
        fillA64(Rp, 128, As);
        fillB(Wq + b * MAT, 128, Bs);
        __syncthreads();
        float acc[2][4][4]; zacc64(acc);
        compute64(As, Bs, acc);
        epi64(Rp, Rp, Wq + b * MAT + mh * 64 * 128, acc);
    }
}

// out tile (128 rows): Y = Zt + Zt@R2 (exact in regs), out = Y + Y@W'3
// grid (16, 8)
__global__ __launch_bounds__(NT) void k_out(const float* __restrict__ Z,
                                            const float* __restrict__ R,
                                            const float* __restrict__ Wq,
                                            float* __restrict__ out) {
    extern __shared__ float sm[];
    float* As = sm; float* Bs = sm + 128 * SA;
    int tile = blockIdx.x, b = blockIdx.y;
    const float* Zt = Z + (b * NN + tile * 128) * 128;
    fillA128(Zt, 128, As);
    fillB(R + b * MAT, 128, Bs);
    __syncthreads();
    float acc[2][8][4]; zacc128(acc);
    compute128(As, Bs, acc);

    // Y (exact fp32) = acc + Zt, kept in acc
    const int lane = threadIdx.x & 31, warp = threadIdx.x >> 5;
    const int r0 = (warp & 3) * 32 + (lane >> 2);
    const int c0 = (warp >> 2) * 64 + 2 * (lane & 3);
#pragma unroll
    for (int i = 0; i < 2; i++)
#pragma unroll
        for (int j = 0; j < 8; j++) {
            int r = r0 + 16 * i, c = c0 + 8 * j;
            acc[i][j][0] += Zt[r * 128 + c];
            acc[i][j][1] += Zt[r * 128 + c + 1];
            acc[i][j][2] += Zt[(r + 8) * 128 + c];
            acc[i][j][3] += Zt[(r + 8) * 128 + c + 1];
        }
    __syncthreads();                 // GEMM1 reads complete
    storeT128(As, acc);              // As <- tf(Y)
    fillB(Wq + b * MAT, 128, Bs);    // Bs <- W'_3
    __syncthreads();
    float acc2[2][8][4]; zacc128(acc2);
    compute128(As, Bs, acc2);

    float* Ct = out + (b * NN + tile * 128) * 128;
#pragma unroll
    for (int i = 0; i < 2; i++)
#pragma unroll
        for (int j = 0; j < 8; j++) {
            int r = r0 + 16 * i, c = c0 + 8 * j;
            *(float2*)(Ct + r * 128 + c) =
                make_float2(acc[i][j][0] + acc2[i][j][0], acc[i][j][1] + acc2[i][j][1]);
            *(float2*)(Ct + (r + 8) * 128 + c) =
                make_float2(acc[i][j][2] + acc2[i][j][2], acc[i][j][3] + acc2[i][j][3]);
        }
}

// ---------------- host ----------------
extern "C" void kernel_launch(void* const* d_in, const int* in_sizes, int n_in,
                              void* d_out, int out_size) {
    const float* Z = (const float*)d_in[0];
    const float* v = (const float*)d_in[1];
    const float* q = (const float*)d_in[2];
    float* out = (float*)d_out;

    cudaFuncSetAttribute(k_g0,  cudaFuncAttributeMaxDynamicSharedMemorySize, SZ_BIG);
    cudaFuncSetAttribute(k_out, cudaFuncAttributeMaxDynamicSharedMemorySize, SZ_BIG);
    cudaFuncSetAttribute(k_TW,  cudaFuncAttributeMaxDynamicSharedMemorySize, SZ_TW);
    cudaFuncSetAttribute(k_C,   cudaFuncAttributeMaxDynamicSharedMemorySize, SZ_C);

    float *pPart, *pG, *pR, *pWp, *pWq;
    cudaGetSymbolAddress((void**)&pPart, g_part);
    cudaGetSymbolAddress((void**)&pG,  g_G);
    cudaGetSymbolAddress((void**)&pR,  g_R);
    cudaGetSymbolAddress((void**)&pWp, g_Wp);
    cudaGetSymbolAddress((void**)&pWq, g_Wq);

    float* Gbuf[2] = { pG, pG + BB * MAT };

    k_g0    <<<dim3(16, BB), NT, SZ_BIG>>>(Z, pPart);
    k_reduce<<<256, 128>>>(pPart, Gbuf[0]);

    int cur = 0;
    for (int l = 0; l < 4; l++) {
        k_TW  <<<dim3(NH, BB, 2), NT, SZ_TW>>>(q, v, Gbuf[cur], pWp, l);
        k_Wsum<<<256, 128>>>(pWp, pWq, pR, l == 0 ? 1 : 0);
        if (l < 3) {
            int zz = (l == 0) ? 1 : 2;
            k_C<<<dim3(2, BB, zz), NT, SZ_C>>>(pWq, Gbuf[cur], pR, Gbuf[cur ^ 1]);
            cur ^= 1;
        }
    }

    k_out<<<dim3(16, BB), NT, SZ_BIG>>>(Z, pR, pWq, out);
}